// round 6
// baseline (speedup 1.0000x reference)
#include <cuda_runtime.h>
#include <math.h>

#define BB 512
#define NN 64
#define MH 128

// ---- scratch (allocation-free) ----
__device__ __align__(16) float g_H[BB * NN * MH];          // 16MB H buffer
__device__ __align__(16) uint2 g_WfP[(MH / 8) * 4 * MH];   // packed tf32 Wfused
__device__ __align__(16) uint2 g_W1P[(MH / 8) * 4 * MH];   // packed tf32 psi_w1
__device__ float g_c0[MH];     // psi_b0 + 63 * phi_b1 @ psi_w0[3:,:]
__device__ float g_sp;         // softplus(bf_scale_raw)

__device__ __forceinline__ float tanh_apx(float v) {
    float y; asm("tanh.approx.f32 %0, %1;" : "=f"(y) : "f"(v)); return y;
}
__device__ __forceinline__ float silu_f(float q) {
    float qh = 0.5f * q;
    float th = tanh_apx(qh);
    return fmaf(qh, th, qh);
}
__device__ __forceinline__ unsigned tf32r(float f) {
    unsigned u; asm("cvt.rna.tf32.f32 %0, %1;" : "=r"(u) : "f"(f)); return u;
}
__device__ __forceinline__ void mma_tf32(float c[4], unsigned a0, unsigned a1,
                                         unsigned a2, unsigned a3,
                                         unsigned b0, unsigned b1) {
    asm("mma.sync.aligned.m16n8k8.row.col.f32.tf32.tf32.f32 "
        "{%0,%1,%2,%3}, {%4,%5,%6,%7}, {%8,%9}, {%0,%1,%2,%3};"
        : "+f"(c[0]), "+f"(c[1]), "+f"(c[2]), "+f"(c[3])
        : "r"(a0), "r"(a1), "r"(a2), "r"(a3), "r"(b0), "r"(b1));
}

// ---------------------------------------------------------------------------
// Kernel 0: precompute (2-half split for latency). 129 blocks x 256 threads.
// ---------------------------------------------------------------------------
__global__ __launch_bounds__(256) void precompute_kernel(
    const float* __restrict__ phi_w1, const float* __restrict__ phi_b1,
    const float* __restrict__ psi_w0, const float* __restrict__ psi_b0,
    const float* __restrict__ psi_w1, const float* __restrict__ bf_scale_raw)
{
    __shared__ float row[MH];
    __shared__ float part[2][MH];
    int t = threadIdx.x;
    int k = blockIdx.x;
    int o = t & 127, hf = t >> 7;
    if (t < MH) row[t] = (k < MH) ? phi_w1[k * MH + t] : phi_b1[t];
    __syncthreads();

    const float* W = psi_w0 + (3 + hf * 64) * MH + o;
    const float* rp = row + hf * 64;
    float a0 = 0.f, a1 = 0.f, a2 = 0.f, a3 = 0.f;
    #pragma unroll 16
    for (int m = 0; m < 64; m += 4) {
        a0 = fmaf(rp[m + 0], W[(m + 0) * MH], a0);
        a1 = fmaf(rp[m + 1], W[(m + 1) * MH], a1);
        a2 = fmaf(rp[m + 2], W[(m + 2) * MH], a2);
        a3 = fmaf(rp[m + 3], W[(m + 3) * MH], a3);
    }
    part[hf][o] = (a0 + a1) + (a2 + a3);
    __syncthreads();
    if (hf == 0) {
        float acc = part[0][o] + part[1][o];
        if (k < MH) {
            int kt = k >> 3, s = k & 7;
            unsigned wf = tf32r(acc);
            unsigned w1 = tf32r(psi_w1[k * MH + o]);
            int idx = (kt * 4 + (s & 3)) * MH + o;
            if (s < 4) { g_WfP[idx].x = wf; g_W1P[idx].x = w1; }
            else       { g_WfP[idx].y = wf; g_W1P[idx].y = w1; }
        } else {
            g_c0[o] = psi_b0[o] + 63.0f * acc;
            if (o == 0) {
                float v = bf_scale_raw[0];
                g_sp = (v > 20.0f) ? v : log1pf(__expf(v));
            }
        }
    }
}

// ---------------------------------------------------------------------------
// phi kernel: 2048 blocks = (batch, quarter of 16 rows) x 256 threads.
// Warp w owns rows R0 + 2w, 2w+1; lane l owns channels 4l..4l+3.
// Same per-element arithmetic as the 123us kernel (bitwise identical H).
// Shared: vs[64][128] 32KB + r1s[64][16] 4KB = 36KB -> 3 CTAs/SM.
// ---------------------------------------------------------------------------
__global__ __launch_bounds__(256, 3) void phi_kernel(
    const float* __restrict__ x,
    const float* __restrict__ W0, const float* __restrict__ b0)
{
    __shared__ __align__(16) float vs[NN * MH];   // 32KB
    __shared__ __align__(16) float r1s[NN * 16];  // [j][ri] 4KB

    int blk = blockIdx.x;
    int b = blk >> 2, R0 = (blk & 3) * 16;
    int t = threadIdx.x, w = t >> 5, l = t & 31;
    int kc = l * 4;
    const float* xb = x + b * (NN * 3);

    // v'_j[k] = 0.5 * sum_d xj_d * (W0[3+d,k] - W0[6+d,k])
    for (int idx = t; idx < NN * MH; idx += 256) {
        int j = idx >> 7, k = idx & 127;
        float xj0 = xb[j * 3 + 0], xj1 = xb[j * 3 + 1], xj2 = xb[j * 3 + 2];
        float vv = xj0 * (W0[3 * MH + k] - W0[6 * MH + k]);
        vv = fmaf(xj1, W0[4 * MH + k] - W0[7 * MH + k], vv);
        vv = fmaf(xj2, W0[5 * MH + k] - W0[8 * MH + k], vv);
        vs[idx] = 0.5f * vv;
    }
    // r1s[j][ri] = dist(R0+ri, j)
    for (int idx = t; idx < NN * 16; idx += 256) {
        int j = idx >> 4, ri = idx & 15;
        int i = R0 + ri;
        float d0 = xb[i * 3 + 0] - xb[j * 3 + 0];
        float d1 = xb[i * 3 + 1] - xb[j * 3 + 1];
        float d2 = xb[i * 3 + 2] - xb[j * 3 + 2];
        r1s[idx] = sqrtf(fmaf(d0, d0, fmaf(d1, d1, fmaf(d2, d2, 1e-12f))));
    }

    float w9h[4], w10h[4];
    float u[2][4];
    {
        float ws0[4], ws1[4], ws2[4], bh[4];
        #pragma unroll
        for (int c = 0; c < 4; c++) {
            int k = kc + c;
            ws0[c] = 0.5f * (W0[0 * MH + k] + W0[6 * MH + k]);
            ws1[c] = 0.5f * (W0[1 * MH + k] + W0[7 * MH + k]);
            ws2[c] = 0.5f * (W0[2 * MH + k] + W0[8 * MH + k]);
            w9h[c]  = 0.5f * W0[9 * MH + k];
            w10h[c] = 0.5f * W0[10 * MH + k];
            bh[c]  = 0.5f * b0[k];
        }
        #pragma unroll
        for (int ii = 0; ii < 2; ii++) {
            int i = R0 + w * 2 + ii;
            float xi0 = xb[i * 3 + 0], xi1 = xb[i * 3 + 1], xi2 = xb[i * 3 + 2];
            #pragma unroll
            for (int c = 0; c < 4; c++)
                u[ii][c] = fmaf(xi2, ws2[c],
                           fmaf(xi1, ws1[c], fmaf(xi0, ws0[c], bh[c])));
        }
    }
    __syncthreads();

    float acc[2][4];
    #pragma unroll
    for (int ii = 0; ii < 2; ii++)
        #pragma unroll
        for (int c = 0; c < 4; c++) acc[ii][c] = 0.0f;

    const float4* vs4 = (const float4*)vs;
    #pragma unroll 4
    for (int j = 0; j < NN; j++) {
        float4 v4 = vs4[j * 32 + l];
        float vc[4] = {v4.x, v4.y, v4.z, v4.w};
        float2 rr = *(const float2*)&r1s[j * 16 + w * 2];
        float r1v[2] = {rr.x, rr.y};
        #pragma unroll
        for (int ii = 0; ii < 2; ii++) {
            float r1 = r1v[ii];
            float r2 = fmaf(r1, r1, -1e-12f);
            #pragma unroll
            for (int c = 0; c < 4; c++) {
                float qh = fmaf(r1, w9h[c], fmaf(r2, w10h[c], u[ii][c] + vc[c]));
                float th = tanh_apx(qh);
                acc[ii][c] = fmaf(qh, th, acc[ii][c] + qh);
            }
        }
    }
    // subtract diagonal (same op order -> same rounding)
    #pragma unroll
    for (int ii = 0; ii < 2; ii++) {
        int ri = w * 2 + ii;
        int ig = R0 + ri;
        float4 v4 = vs4[ig * 32 + l];
        float vc[4] = {v4.x, v4.y, v4.z, v4.w};
        float r1 = r1s[ig * 16 + ri];
        float r2 = fmaf(r1, r1, -1e-12f);
        #pragma unroll
        for (int c = 0; c < 4; c++) {
            float qh = fmaf(r1, w9h[c], fmaf(r2, w10h[c], u[ii][c] + vc[c]));
            float th = tanh_apx(qh);
            acc[ii][c] -= fmaf(qh, th, qh);
        }
    }
    // store H (coalesced float4 per row)
    #pragma unroll
    for (int ii = 0; ii < 2; ii++) {
        int ig = R0 + w * 2 + ii;
        *(float4*)&g_H[((size_t)(b * NN) + ig) * MH + kc] =
            make_float4(acc[ii][0], acc[ii][1], acc[ii][2], acc[ii][3]);
    }
}

// ---------------------------------------------------------------------------
// psi kernel: 512 blocks x 256 threads. Stage H from global, then the tf32
// mma pipeline (identical to the 123us kernel's phase 2).
// ---------------------------------------------------------------------------
__global__ __launch_bounds__(256, 2) void psi_kernel(
    const float* __restrict__ x,
    const float* __restrict__ psi_w0, const float* __restrict__ psi_b1,
    const float* __restrict__ psi_w2, const float* __restrict__ psi_b2,
    float* __restrict__ out)
{
    __shared__ __align__(16) float smem_f[8832];
    float* sb = smem_f;             // H / h1, 64 rows stride 132
    float* part = smem_f + 8448;    // partials [2][64][3]

    int b = blockIdx.x;
    int t = threadIdx.x;
    int w = t >> 5, l = t & 31;
    const float* xb = x + b * (NN * 3);

    // stage H -> sb (stride 132)
    {
        const float4* Hg = (const float4*)(g_H + (size_t)b * NN * MH);
        for (int i4 = t; i4 < NN * MH / 4; i4 += 256) {
            int row = i4 >> 5, kq = i4 & 31;
            *(float4*)&sb[row * 132 + kq * 4] = Hg[i4];
        }
    }
    __syncthreads();

    int mi = w & 3, nh = w >> 2;
    int gi = l >> 2, qi = l & 3;
    int rA = mi * 16 + gi;          // rows rA and rA+8
    int nbase = nh * 64;

    float C[8][4];
    float xr0[3] = {xb[rA * 3 + 0], xb[rA * 3 + 1], xb[rA * 3 + 2]};
    float xr1[3] = {xb[(rA + 8) * 3 + 0], xb[(rA + 8) * 3 + 1], xb[(rA + 8) * 3 + 2]};

    // C init: c0 + x @ psi_w0[0:3]  (exact fp32)
    #pragma unroll
    for (int tt = 0; tt < 8; tt++) {
        int nc = nbase + tt * 8 + qi * 2;
        #pragma unroll
        for (int h = 0; h < 2; h++) {
            float cc = g_c0[nc + h];
            float p0 = psi_w0[0 * MH + nc + h];
            float p1 = psi_w0[1 * MH + nc + h];
            float p2 = psi_w0[2 * MH + nc + h];
            C[tt][h]     = fmaf(xr0[2], p2, fmaf(xr0[1], p1, fmaf(xr0[0], p0, cc)));
            C[tt][2 + h] = fmaf(xr1[2], p2, fmaf(xr1[1], p1, fmaf(xr1[0], p0, cc)));
        }
    }

    // layer A: C += H @ Wfused
    {
        const float* sA0 = &sb[rA * 132];
        const float* sA1 = &sb[(rA + 8) * 132];
        const uint2* wp = &g_WfP[qi * MH + nbase + gi];
        #pragma unroll 1
        for (int kt = 0; kt < 16; kt++) {
            int k0 = kt * 8;
            unsigned a0 = tf32r(sA0[k0 + qi]);
            unsigned a1 = tf32r(sA1[k0 + qi]);
            unsigned a2 = tf32r(sA0[k0 + qi + 4]);
            unsigned a3 = tf32r(sA1[k0 + qi + 4]);
            #pragma unroll
            for (int tt = 0; tt < 8; tt++) {
                uint2 bb = wp[tt * 8];
                mma_tf32(C[tt], a0, a1, a2, a3, bb.x, bb.y);
            }
            wp += 4 * MH;
        }
    }
    __syncthreads();   // all H reads done before overwriting with h1

    // silu -> h1 in shared
    #pragma unroll
    for (int tt = 0; tt < 8; tt++) {
        int nc = nbase + tt * 8 + qi * 2;
        *(float2*)&sb[rA * 132 + nc] =
            make_float2(silu_f(C[tt][0]), silu_f(C[tt][1]));
        *(float2*)&sb[(rA + 8) * 132 + nc] =
            make_float2(silu_f(C[tt][2]), silu_f(C[tt][3]));
    }
    __syncthreads();

    // layer B: C = psi_b1 + h1 @ psi_w1
    #pragma unroll
    for (int tt = 0; tt < 8; tt++) {
        int nc = nbase + tt * 8 + qi * 2;
        float bb0 = psi_b1[nc], bb1 = psi_b1[nc + 1];
        C[tt][0] = bb0; C[tt][1] = bb1; C[tt][2] = bb0; C[tt][3] = bb1;
    }
    {
        const float* sA0 = &sb[rA * 132];
        const float* sA1 = &sb[(rA + 8) * 132];
        const uint2* wp = &g_W1P[qi * MH + nbase + gi];
        #pragma unroll 1
        for (int kt = 0; kt < 16; kt++) {
            int k0 = kt * 8;
            unsigned a0 = tf32r(sA0[k0 + qi]);
            unsigned a1 = tf32r(sA1[k0 + qi]);
            unsigned a2 = tf32r(sA0[k0 + qi + 4]);
            unsigned a3 = tf32r(sA1[k0 + qi + 4]);
            #pragma unroll
            for (int tt = 0; tt < 8; tt++) {
                uint2 bb = wp[tt * 8];
                mma_tf32(C[tt], a0, a1, a2, a3, bb.x, bb.y);
            }
            wp += 4 * MH;
        }
    }

    // layer C: silu -> partial projection onto psi_w2 (exact fp32)
    float p0[3] = {0.f, 0.f, 0.f}, p1[3] = {0.f, 0.f, 0.f};
    #pragma unroll
    for (int tt = 0; tt < 8; tt++) {
        int nc = nbase + tt * 8 + qi * 2;
        float s00 = silu_f(C[tt][0]), s01 = silu_f(C[tt][1]);
        float s10 = silu_f(C[tt][2]), s11 = silu_f(C[tt][3]);
        #pragma unroll
        for (int oc = 0; oc < 3; oc++) {
            float wa = psi_w2[nc * 3 + oc];
            float wb = psi_w2[(nc + 1) * 3 + oc];
            p0[oc] = fmaf(s01, wb, fmaf(s00, wa, p0[oc]));
            p1[oc] = fmaf(s11, wb, fmaf(s10, wa, p1[oc]));
        }
    }
    #pragma unroll
    for (int oc = 0; oc < 3; oc++) {
        p0[oc] += __shfl_xor_sync(0xffffffffu, p0[oc], 1);
        p0[oc] += __shfl_xor_sync(0xffffffffu, p0[oc], 2);
        p1[oc] += __shfl_xor_sync(0xffffffffu, p1[oc], 1);
        p1[oc] += __shfl_xor_sync(0xffffffffu, p1[oc], 2);
    }
    if (qi == 0) {
        #pragma unroll
        for (int oc = 0; oc < 3; oc++) {
            part[nh * 192 + rA * 3 + oc] = p0[oc];
            part[nh * 192 + (rA + 8) * 3 + oc] = p1[oc];
        }
    }
    __syncthreads();

    if (t < 192) {
        int r = t / 3, oc = t - r * 3;
        float p = part[r * 3 + oc] + part[192 + r * 3 + oc] + psi_b2[oc];
        out[(b * NN + r) * 3 + oc] = tanhf(p) * g_sp;
    }
}

// ---------------------------------------------------------------------------
// Inputs (metadata order): 0 x, 1 spin(unused), 2 phi_w0, 3 phi_b0, 4 phi_w1,
// 5 phi_b1, 6 psi_w0, 7 psi_b0, 8 psi_w1, 9 psi_b1, 10 psi_w2, 11 psi_b2,
// 12 bf_scale_raw. Output: float32 (512,64,3).
// ---------------------------------------------------------------------------
extern "C" void kernel_launch(void* const* d_in, const int* in_sizes, int n_in,
                              void* d_out, int out_size)
{
    const float* x      = (const float*)d_in[0];
    const float* phi_w0 = (const float*)d_in[2];
    const float* phi_b0 = (const float*)d_in[3];
    const float* phi_w1 = (const float*)d_in[4];
    const float* phi_b1 = (const float*)d_in[5];
    const float* psi_w0 = (const float*)d_in[6];
    const float* psi_b0 = (const float*)d_in[7];
    const float* psi_w1 = (const float*)d_in[8];
    const float* psi_b1 = (const float*)d_in[9];
    const float* psi_w2 = (const float*)d_in[10];
    const float* psi_b2 = (const float*)d_in[11];
    const float* bf     = (const float*)d_in[12];
    float* out = (float*)d_out;

    precompute_kernel<<<MH + 1, 256>>>(phi_w1, phi_b1, psi_w0, psi_b0, psi_w1, bf);
    phi_kernel<<<BB * 4, 256>>>(x, phi_w0, phi_b0);
    psi_kernel<<<BB, 256>>>(x, psi_w0, psi_b1, psi_w2, psi_b2, out);
}

// round 8
// speedup vs baseline: 1.2234x; 1.2234x over previous
#include <cuda_runtime.h>
#include <math.h>

#define BB 512
#define NN 64
#define MH 128

// ---- scratch (allocation-free) ----
__device__ __align__(16) uint2 g_WfP[(MH / 8) * 4 * MH];   // packed tf32 Wfused
__device__ __align__(16) uint2 g_W1P[(MH / 8) * 4 * MH];   // packed tf32 psi_w1
__device__ float g_c0[MH];     // psi_b0 + 63 * phi_b1 @ psi_w0[3:,:]
__device__ float g_sp;         // softplus(bf_scale_raw)

__device__ __forceinline__ float tanh_apx(float v) {
    float y; asm("tanh.approx.f32 %0, %1;" : "=f"(y) : "f"(v)); return y;
}
__device__ __forceinline__ float silu_f(float q) {
    float qh = 0.5f * q;
    float th = tanh_apx(qh);
    return fmaf(qh, th, qh);
}
__device__ __forceinline__ unsigned tf32r(float f) {
    unsigned u; asm("cvt.rna.tf32.f32 %0, %1;" : "=r"(u) : "f"(f)); return u;
}
__device__ __forceinline__ void mma_tf32(float c[4], unsigned a0, unsigned a1,
                                         unsigned a2, unsigned a3,
                                         unsigned b0, unsigned b1) {
    asm("mma.sync.aligned.m16n8k8.row.col.f32.tf32.tf32.f32 "
        "{%0,%1,%2,%3}, {%4,%5,%6,%7}, {%8,%9}, {%0,%1,%2,%3};"
        : "+f"(c[0]), "+f"(c[1]), "+f"(c[2]), "+f"(c[3])
        : "r"(a0), "r"(a1), "r"(a2), "r"(a3), "r"(b0), "r"(b1));
}

// ---------------------------------------------------------------------------
// Kernel 0: precompute (2-half split). 129 blocks x 256 threads.
// ---------------------------------------------------------------------------
__global__ __launch_bounds__(256) void precompute_kernel(
    const float* __restrict__ phi_w1, const float* __restrict__ phi_b1,
    const float* __restrict__ psi_w0, const float* __restrict__ psi_b0,
    const float* __restrict__ psi_w1, const float* __restrict__ bf_scale_raw)
{
    __shared__ float row[MH];
    __shared__ float part[2][MH];
    int t = threadIdx.x;
    int k = blockIdx.x;
    int o = t & 127, hf = t >> 7;
    if (t < MH) row[t] = (k < MH) ? phi_w1[k * MH + t] : phi_b1[t];
    __syncthreads();

    const float* W = psi_w0 + (3 + hf * 64) * MH + o;
    const float* rp = row + hf * 64;
    float a0 = 0.f, a1 = 0.f, a2 = 0.f, a3 = 0.f;
    #pragma unroll 16
    for (int m = 0; m < 64; m += 4) {
        a0 = fmaf(rp[m + 0], W[(m + 0) * MH], a0);
        a1 = fmaf(rp[m + 1], W[(m + 1) * MH], a1);
        a2 = fmaf(rp[m + 2], W[(m + 2) * MH], a2);
        a3 = fmaf(rp[m + 3], W[(m + 3) * MH], a3);
    }
    part[hf][o] = (a0 + a1) + (a2 + a3);
    __syncthreads();
    if (hf == 0) {
        float acc = part[0][o] + part[1][o];
        if (k < MH) {
            int kt = k >> 3, s = k & 7;
            unsigned wf = tf32r(acc);
            unsigned w1 = tf32r(psi_w1[k * MH + o]);
            int idx = (kt * 4 + (s & 3)) * MH + o;
            if (s < 4) { g_WfP[idx].x = wf; g_W1P[idx].x = w1; }
            else       { g_WfP[idx].y = wf; g_W1P[idx].y = w1; }
        } else {
            g_c0[o] = psi_b0[o] + 63.0f * acc;
            if (o == 0) {
                float v = bf_scale_raw[0];
                g_sp = (v > 20.0f) ? v : log1pf(__expf(v));
            }
        }
    }
}

// ---------------------------------------------------------------------------
// Fused kernel: 512 blocks x 256 threads (8 warps). 48KB shared, phase-aliased:
//   phase1: vs[0..8192) r1s[8192..12288)
//   sums:   SV[8448..8576) S1[8576..8640) S2[8640..8704)  (written after all
//           phase-1 reads retire; disjoint from H overlay [0..8444))
//   phase2: sb[0..8448) stride-132 H/h1; part[8448..8832)
// Phase 1: silu = linear(closed form from column sums) + tanh part (4fp+1MUFU).
// Phase 2: tf32 mma psi (identical to the 123us kernel).
// ---------------------------------------------------------------------------
__global__ __launch_bounds__(256, 2) void fused_kernel(
    const float* __restrict__ x,
    const float* __restrict__ W0, const float* __restrict__ b0,
    const float* __restrict__ psi_w0, const float* __restrict__ psi_b1,
    const float* __restrict__ psi_w2, const float* __restrict__ psi_b2,
    float* __restrict__ out)
{
    __shared__ __align__(16) float smem_f[12288];   // 48KB exactly
    float* vs  = smem_f;            // phase1
    float* r1s = smem_f + 8192;     // phase1
    float* sb  = smem_f;            // phase2 H/h1
    float* SV  = smem_f + 8448;     // 128
    float* S1  = smem_f + 8576;     // 64
    float* S2  = smem_f + 8640;     // 64
    float* part = smem_f + 8448;    // phase2 partials (after SV/S1/S2 dead)

    int b = blockIdx.x;
    int t = threadIdx.x;
    int w = t >> 5, l = t & 31;
    int r0 = w * 8;
    int kc = l * 4;
    const float* xb = x + b * (NN * 3);

    // ---------------- Phase 1 setup ----------------
    for (int idx = t; idx < NN * MH; idx += 256) {
        int j = idx >> 7, k = idx & 127;
        float xj0 = xb[j * 3 + 0], xj1 = xb[j * 3 + 1], xj2 = xb[j * 3 + 2];
        float vv = xj0 * (W0[3 * MH + k] - W0[6 * MH + k]);
        vv = fmaf(xj1, W0[4 * MH + k] - W0[7 * MH + k], vv);
        vv = fmaf(xj2, W0[5 * MH + k] - W0[8 * MH + k], vv);
        vs[idx] = 0.5f * vv;
    }
    for (int idx = t; idx < NN * NN; idx += 256) {
        int j = idx >> 6, i = idx & 63;
        float d0 = xb[i * 3 + 0] - xb[j * 3 + 0];
        float d1 = xb[i * 3 + 1] - xb[j * 3 + 1];
        float d2 = xb[i * 3 + 2] - xb[j * 3 + 2];
        r1s[idx] = sqrtf(fmaf(d0, d0, fmaf(d1, d1, fmaf(d2, d2, 1e-12f))));
    }

    float w9h[4], w10h[4];
    float u[8][4];
    {
        float ws0[4], ws1[4], ws2[4], bh[4];
        #pragma unroll
        for (int c = 0; c < 4; c++) {
            int k = kc + c;
            ws0[c] = 0.5f * (W0[0 * MH + k] + W0[6 * MH + k]);
            ws1[c] = 0.5f * (W0[1 * MH + k] + W0[7 * MH + k]);
            ws2[c] = 0.5f * (W0[2 * MH + k] + W0[8 * MH + k]);
            w9h[c]  = 0.5f * W0[9 * MH + k];
            w10h[c] = 0.5f * W0[10 * MH + k];
            bh[c]  = 0.5f * b0[k];
        }
        #pragma unroll
        for (int ii = 0; ii < 8; ii++) {
            int i = r0 + ii;
            float xi0 = xb[i * 3 + 0], xi1 = xb[i * 3 + 1], xi2 = xb[i * 3 + 2];
            #pragma unroll
            for (int c = 0; c < 4; c++)
                u[ii][c] = fmaf(xi2, ws2[c],
                           fmaf(xi1, ws1[c], fmaf(xi0, ws0[c], bh[c])));
        }
    }
    __syncthreads();

    // ---------------- Phase 1 main loop: tanh part only ----------------
    float acc[8][4];
    #pragma unroll
    for (int ii = 0; ii < 8; ii++)
        #pragma unroll
        for (int c = 0; c < 4; c++) acc[ii][c] = 0.0f;

    const float4* vs4 = (const float4*)vs;
    #pragma unroll 2
    for (int j = 0; j < NN; j++) {
        float4 v4 = vs4[j * 32 + l];
        float vc[4] = {v4.x, v4.y, v4.z, v4.w};
        float4 ra = *(const float4*)&r1s[j * NN + r0];
        float4 rb = *(const float4*)&r1s[j * NN + r0 + 4];
        float r1v[8] = {ra.x, ra.y, ra.z, ra.w, rb.x, rb.y, rb.z, rb.w};
        #pragma unroll
        for (int ii = 0; ii < 8; ii++) {
            float r1 = r1v[ii];
            float r2 = fmaf(r1, r1, -1e-12f);
            #pragma unroll
            for (int c = 0; c < 4; c++) {
                float qh = fmaf(r1, w9h[c], fmaf(r2, w10h[c], u[ii][c] + vc[c]));
                float th = tanh_apx(qh);
                acc[ii][c] = fmaf(qh, th, acc[ii][c]);   // tanh part only
            }
        }
    }
    // subtract full diagonal silu (linear sums below include j==i)
    #pragma unroll
    for (int ii = 0; ii < 8; ii++) {
        int ig = r0 + ii;
        float4 v4 = vs4[ig * 32 + l];
        float vc[4] = {v4.x, v4.y, v4.z, v4.w};
        float r1 = r1s[ig * NN + ig];
        float r2 = fmaf(r1, r1, -1e-12f);
        #pragma unroll
        for (int c = 0; c < 4; c++) {
            float qh = fmaf(r1, w9h[c], fmaf(r2, w10h[c], u[ii][c] + vc[c]));
            float th = tanh_apx(qh);
            acc[ii][c] -= fmaf(qh, th, qh);   // qh + qh*th
        }
    }

    // ---------------- column sums (registers first) ----------------
    float rs1 = 0.f, rs2 = 0.f, rsv = 0.f;
    if (t < NN) {
        #pragma unroll 8
        for (int j = 0; j < NN; j++) {
            float r1 = r1s[j * NN + t];       // column read: conflict-free
            rs1 += r1;
            rs2 += fmaf(r1, r1, -1e-12f);
        }
    } else if (t < NN + MH) {
        int c = t - NN;
        #pragma unroll 8
        for (int j = 0; j < NN; j++) rsv += vs[j * MH + c];
    }
    __syncthreads();   // all phase-1 shared reads retired
    if (t < NN) { S1[t] = rs1; S2[t] = rs2; }
    else if (t < NN + MH) { SV[t - NN] = rsv; }
    __syncthreads();   // sums visible

    // H = linear + acc ; overlay into sb (stride 132, [0..8444) only)
    #pragma unroll
    for (int ii = 0; ii < 8; ii++) {
        int ig = r0 + ii;
        float s1 = S1[ig], s2 = S2[ig];
        float hv[4];
        #pragma unroll
        for (int c = 0; c < 4; c++) {
            float lin = fmaf(64.0f, u[ii][c], SV[kc + c]);
            lin = fmaf(w9h[c], s1, lin);
            lin = fmaf(w10h[c], s2, lin);
            hv[c] = lin + acc[ii][c];
        }
        *(float4*)&sb[ig * 132 + kc] = make_float4(hv[0], hv[1], hv[2], hv[3]);
    }
    __syncthreads();

    // ---------------- Phase 2: psi via tf32 mma ----------------
    int mi = w & 3, nh = w >> 2;
    int gi = l >> 2, qi = l & 3;
    int rA = mi * 16 + gi;          // rows rA and rA+8
    int nbase = nh * 64;

    float C[8][4];
    float xr0[3] = {xb[rA * 3 + 0], xb[rA * 3 + 1], xb[rA * 3 + 2]};
    float xr1[3] = {xb[(rA + 8) * 3 + 0], xb[(rA + 8) * 3 + 1], xb[(rA + 8) * 3 + 2]};

    #pragma unroll
    for (int tt = 0; tt < 8; tt++) {
        int nc = nbase + tt * 8 + qi * 2;
        #pragma unroll
        for (int h = 0; h < 2; h++) {
            float cc = g_c0[nc + h];
            float p0 = psi_w0[0 * MH + nc + h];
            float p1 = psi_w0[1 * MH + nc + h];
            float p2 = psi_w0[2 * MH + nc + h];
            C[tt][h]     = fmaf(xr0[2], p2, fmaf(xr0[1], p1, fmaf(xr0[0], p0, cc)));
            C[tt][2 + h] = fmaf(xr1[2], p2, fmaf(xr1[1], p1, fmaf(xr1[0], p0, cc)));
        }
    }

    // layer A: C += H @ Wfused
    {
        const float* sA0 = &sb[rA * 132];
        const float* sA1 = &sb[(rA + 8) * 132];
        const uint2* wp = &g_WfP[qi * MH + nbase + gi];
        #pragma unroll 1
        for (int kt = 0; kt < 16; kt++) {
            int k0 = kt * 8;
            unsigned a0 = tf32r(sA0[k0 + qi]);
            unsigned a1 = tf32r(sA1[k0 + qi]);
            unsigned a2 = tf32r(sA0[k0 + qi + 4]);
            unsigned a3 = tf32r(sA1[k0 + qi + 4]);
            #pragma unroll
            for (int tt = 0; tt < 8; tt++) {
                uint2 bb = wp[tt * 8];
                mma_tf32(C[tt], a0, a1, a2, a3, bb.x, bb.y);
            }
            wp += 4 * MH;
        }
    }
    __syncthreads();

    // silu -> h1 in shared
    #pragma unroll
    for (int tt = 0; tt < 8; tt++) {
        int nc = nbase + tt * 8 + qi * 2;
        *(float2*)&sb[rA * 132 + nc] =
            make_float2(silu_f(C[tt][0]), silu_f(C[tt][1]));
        *(float2*)&sb[(rA + 8) * 132 + nc] =
            make_float2(silu_f(C[tt][2]), silu_f(C[tt][3]));
    }
    __syncthreads();

    // layer B: C = psi_b1 + h1 @ psi_w1
    #pragma unroll
    for (int tt = 0; tt < 8; tt++) {
        int nc = nbase + tt * 8 + qi * 2;
        float bb0 = psi_b1[nc], bb1 = psi_b1[nc + 1];
        C[tt][0] = bb0; C[tt][1] = bb1; C[tt][2] = bb0; C[tt][3] = bb1;
    }
    {
        const float* sA0 = &sb[rA * 132];
        const float* sA1 = &sb[(rA + 8) * 132];
        const uint2* wp = &g_W1P[qi * MH + nbase + gi];
        #pragma unroll 1
        for (int kt = 0; kt < 16; kt++) {
            int k0 = kt * 8;
            unsigned a0 = tf32r(sA0[k0 + qi]);
            unsigned a1 = tf32r(sA1[k0 + qi]);
            unsigned a2 = tf32r(sA0[k0 + qi + 4]);
            unsigned a3 = tf32r(sA1[k0 + qi + 4]);
            #pragma unroll
            for (int tt = 0; tt < 8; tt++) {
                uint2 bb = wp[tt * 8];
                mma_tf32(C[tt], a0, a1, a2, a3, bb.x, bb.y);
            }
            wp += 4 * MH;
        }
    }

    // layer C: silu -> partial projection onto psi_w2 (exact fp32)
    float p0[3] = {0.f, 0.f, 0.f}, p1[3] = {0.f, 0.f, 0.f};
    #pragma unroll
    for (int tt = 0; tt < 8; tt++) {
        int nc = nbase + tt * 8 + qi * 2;
        float s00 = silu_f(C[tt][0]), s01 = silu_f(C[tt][1]);
        float s10 = silu_f(C[tt][2]), s11 = silu_f(C[tt][3]);
        #pragma unroll
        for (int oc = 0; oc < 3; oc++) {
            float wa = psi_w2[nc * 3 + oc];
            float wb = psi_w2[(nc + 1) * 3 + oc];
            p0[oc] = fmaf(s01, wb, fmaf(s00, wa, p0[oc]));
            p1[oc] = fmaf(s11, wb, fmaf(s10, wa, p1[oc]));
        }
    }
    #pragma unroll
    for (int oc = 0; oc < 3; oc++) {
        p0[oc] += __shfl_xor_sync(0xffffffffu, p0[oc], 1);
        p0[oc] += __shfl_xor_sync(0xffffffffu, p0[oc], 2);
        p1[oc] += __shfl_xor_sync(0xffffffffu, p1[oc], 1);
        p1[oc] += __shfl_xor_sync(0xffffffffu, p1[oc], 2);
    }
    if (qi == 0) {
        #pragma unroll
        for (int oc = 0; oc < 3; oc++) {
            part[nh * 192 + rA * 3 + oc] = p0[oc];
            part[nh * 192 + (rA + 8) * 3 + oc] = p1[oc];
        }
    }
    __syncthreads();

    if (t < 192) {
        int r = t / 3, oc = t - r * 3;
        float p = part[r * 3 + oc] + part[192 + r * 3 + oc] + psi_b2[oc];
        out[(b * NN + r) * 3 + oc] = tanhf(p) * g_sp;
    }
}

// ---------------------------------------------------------------------------
// Inputs (metadata order): 0 x, 1 spin(unused), 2 phi_w0, 3 phi_b0, 4 phi_w1,
// 5 phi_b1, 6 psi_w0, 7 psi_b0, 8 psi_w1, 9 psi_b1, 10 psi_w2, 11 psi_b2,
// 12 bf_scale_raw. Output: float32 (512,64,3).
// ---------------------------------------------------------------------------
extern "C" void kernel_launch(void* const* d_in, const int* in_sizes, int n_in,
                              void* d_out, int out_size)
{
    const float* x      = (const float*)d_in[0];
    const float* phi_w0 = (const float*)d_in[2];
    const float* phi_b0 = (const float*)d_in[3];
    const float* phi_w1 = (const float*)d_in[4];
    const float* phi_b1 = (const float*)d_in[5];
    const float* psi_w0 = (const float*)d_in[6];
    const float* psi_b0 = (const float*)d_in[7];
    const float* psi_w1 = (const float*)d_in[8];
    const float* psi_b1 = (const float*)d_in[9];
    const float* psi_w2 = (const float*)d_in[10];
    const float* psi_b2 = (const float*)d_in[11];
    const float* bf     = (const float*)d_in[12];
    float* out = (float*)d_out;

    precompute_kernel<<<MH + 1, 256>>>(phi_w1, phi_b1, psi_w0, psi_b0, psi_w1, bf);
    fused_kernel<<<BB, 256>>>(x, phi_w0, phi_b0, psi_w0,
                              psi_b1, psi_w2, psi_b2, out);
}

// round 9
// speedup vs baseline: 1.3459x; 1.1001x over previous
#include <cuda_runtime.h>
#include <math.h>

#define BB 512
#define NN 64
#define MH 128
#define NR 32    // rows per block (half batch)

// ---- scratch (allocation-free) ----
__device__ __align__(16) uint2 g_WfP[(MH / 8) * 4 * MH];   // packed tf32 Wfused
__device__ __align__(16) uint2 g_W1P[(MH / 8) * 4 * MH];   // packed tf32 psi_w1
__device__ float g_c0[MH];     // psi_b0 + 63 * phi_b1 @ psi_w0[3:,:]
__device__ float g_sp;         // softplus(bf_scale_raw)

__device__ __forceinline__ float tanh_apx(float v) {
    float y; asm("tanh.approx.f32 %0, %1;" : "=f"(y) : "f"(v)); return y;
}
__device__ __forceinline__ float silu_f(float q) {
    float qh = 0.5f * q;
    float th = tanh_apx(qh);
    return fmaf(qh, th, qh);
}
__device__ __forceinline__ unsigned tf32r(float f) {
    unsigned u; asm("cvt.rna.tf32.f32 %0, %1;" : "=r"(u) : "f"(f)); return u;
}
__device__ __forceinline__ void mma_tf32(float c[4], unsigned a0, unsigned a1,
                                         unsigned a2, unsigned a3,
                                         unsigned b0, unsigned b1) {
    asm("mma.sync.aligned.m16n8k8.row.col.f32.tf32.tf32.f32 "
        "{%0,%1,%2,%3}, {%4,%5,%6,%7}, {%8,%9}, {%0,%1,%2,%3};"
        : "+f"(c[0]), "+f"(c[1]), "+f"(c[2]), "+f"(c[3])
        : "r"(a0), "r"(a1), "r"(a2), "r"(a3), "r"(b0), "r"(b1));
}

// ---------------------------------------------------------------------------
// Kernel 0: precompute (2-half split). 129 blocks x 256 threads.
// ---------------------------------------------------------------------------
__global__ __launch_bounds__(256) void precompute_kernel(
    const float* __restrict__ phi_w1, const float* __restrict__ phi_b1,
    const float* __restrict__ psi_w0, const float* __restrict__ psi_b0,
    const float* __restrict__ psi_w1, const float* __restrict__ bf_scale_raw)
{
    __shared__ float row[MH];
    __shared__ float part[2][MH];
    int t = threadIdx.x;
    int k = blockIdx.x;
    int o = t & 127, hf = t >> 7;
    if (t < MH) row[t] = (k < MH) ? phi_w1[k * MH + t] : phi_b1[t];
    __syncthreads();

    const float* W = psi_w0 + (3 + hf * 64) * MH + o;
    const float* rp = row + hf * 64;
    float a0 = 0.f, a1 = 0.f, a2 = 0.f, a3 = 0.f;
    #pragma unroll 16
    for (int m = 0; m < 64; m += 4) {
        a0 = fmaf(rp[m + 0], W[(m + 0) * MH], a0);
        a1 = fmaf(rp[m + 1], W[(m + 1) * MH], a1);
        a2 = fmaf(rp[m + 2], W[(m + 2) * MH], a2);
        a3 = fmaf(rp[m + 3], W[(m + 3) * MH], a3);
    }
    part[hf][o] = (a0 + a1) + (a2 + a3);
    __syncthreads();
    if (hf == 0) {
        float acc = part[0][o] + part[1][o];
        if (k < MH) {
            int kt = k >> 3, s = k & 7;
            unsigned wf = tf32r(acc);
            unsigned w1 = tf32r(psi_w1[k * MH + o]);
            int idx = (kt * 4 + (s & 3)) * MH + o;
            if (s < 4) { g_WfP[idx].x = wf; g_W1P[idx].x = w1; }
            else       { g_WfP[idx].y = wf; g_W1P[idx].y = w1; }
        } else {
            g_c0[o] = psi_b0[o] + 63.0f * acc;
            if (o == 0) {
                float v = bf_scale_raw[0];
                g_sp = (v > 20.0f) ? v : log1pf(__expf(v));
            }
        }
    }
}

// ---------------------------------------------------------------------------
// Fused kernel: 1024 blocks = (batch, 32-row half) x 256 threads, 3 CTAs/SM.
// Phase 1 (phi): warp w owns local rows w*4..+3; lane l owns ch 4l..4l+3.
//   silu = linear (closed form from column sums) + tanh part.
// Phase 2 (psi): rows R0..R0+31 only (row-local), tf32 mma, 16x32 per warp.
// Shared ~42KB: vs[8192] r1s[2048] SV/S1/S2[192] part[384]; H aliases vs.
// ---------------------------------------------------------------------------
__global__ __launch_bounds__(256, 3) void fused_kernel(
    const float* __restrict__ x,
    const float* __restrict__ W0, const float* __restrict__ b0,
    const float* __restrict__ psi_w0, const float* __restrict__ psi_b1,
    const float* __restrict__ psi_w2, const float* __restrict__ psi_b2,
    float* __restrict__ out)
{
    __shared__ __align__(16) float vs[NN * MH];    // 32KB; later H (stride 132)
    __shared__ __align__(16) float r1s[NN * NR];   // [j][li] 8KB
    __shared__ float SV[MH];
    __shared__ float S1[NR];
    __shared__ float S2[NR];
    __shared__ float part[4 * NR * 3];             // [nh][row][oc]

    int blk = blockIdx.x;
    int b = blk >> 1, R0 = (blk & 1) * NR;
    int t = threadIdx.x;
    int w = t >> 5, l = t & 31;
    int lw = w * 4;          // local row base for this warp (phi)
    int kc = l * 4;
    const float* xb = x + b * (NN * 3);
    float* sb = vs;          // phase2: H/h1, 32 rows stride 132 (<=4224)

    // ---------------- Phase 1 setup ----------------
    for (int idx = t; idx < NN * MH; idx += 256) {
        int j = idx >> 7, k = idx & 127;
        float xj0 = xb[j * 3 + 0], xj1 = xb[j * 3 + 1], xj2 = xb[j * 3 + 2];
        float vv = xj0 * (W0[3 * MH + k] - W0[6 * MH + k]);
        vv = fmaf(xj1, W0[4 * MH + k] - W0[7 * MH + k], vv);
        vv = fmaf(xj2, W0[5 * MH + k] - W0[8 * MH + k], vv);
        vs[idx] = 0.5f * vv;
    }
    for (int idx = t; idx < NN * NR; idx += 256) {
        int j = idx >> 5, li = idx & 31;
        int i = R0 + li;
        float d0 = xb[i * 3 + 0] - xb[j * 3 + 0];
        float d1 = xb[i * 3 + 1] - xb[j * 3 + 1];
        float d2 = xb[i * 3 + 2] - xb[j * 3 + 2];
        r1s[idx] = sqrtf(fmaf(d0, d0, fmaf(d1, d1, fmaf(d2, d2, 1e-12f))));
    }

    float w9h[4], w10h[4];
    float u[4][4];
    {
        float ws0[4], ws1[4], ws2[4], bh[4];
        #pragma unroll
        for (int c = 0; c < 4; c++) {
            int k = kc + c;
            ws0[c] = 0.5f * (W0[0 * MH + k] + W0[6 * MH + k]);
            ws1[c] = 0.5f * (W0[1 * MH + k] + W0[7 * MH + k]);
            ws2[c] = 0.5f * (W0[2 * MH + k] + W0[8 * MH + k]);
            w9h[c]  = 0.5f * W0[9 * MH + k];
            w10h[c] = 0.5f * W0[10 * MH + k];
            bh[c]  = 0.5f * b0[k];
        }
        #pragma unroll
        for (int ii = 0; ii < 4; ii++) {
            int i = R0 + lw + ii;
            float xi0 = xb[i * 3 + 0], xi1 = xb[i * 3 + 1], xi2 = xb[i * 3 + 2];
            #pragma unroll
            for (int c = 0; c < 4; c++)
                u[ii][c] = fmaf(xi2, ws2[c],
                           fmaf(xi1, ws1[c], fmaf(xi0, ws0[c], bh[c])));
        }
    }
    __syncthreads();

    // ---------------- column sums (own region, no aliasing) ----------------
    if (t < NR) {
        float s1 = 0.f, s2 = 0.f;
        #pragma unroll 8
        for (int j = 0; j < NN; j++) {
            float r1 = r1s[j * NR + t];
            s1 += r1;
            s2 += fmaf(r1, r1, -1e-12f);
        }
        S1[t] = s1; S2[t] = s2;
    } else if (t < NR + MH) {
        int c = t - NR;
        float sv = 0.f;
        #pragma unroll 8
        for (int j = 0; j < NN; j++) sv += vs[j * MH + c];
        SV[c] = sv;
    }

    // ---------------- Phase 1 main loop: tanh part only ----------------
    float acc[4][4];
    #pragma unroll
    for (int ii = 0; ii < 4; ii++)
        #pragma unroll
        for (int c = 0; c < 4; c++) acc[ii][c] = 0.0f;

    const float4* vs4 = (const float4*)vs;
    #pragma unroll 2
    for (int j = 0; j < NN; j++) {
        float4 v4 = vs4[j * 32 + l];
        float vc[4] = {v4.x, v4.y, v4.z, v4.w};
        float4 ra = *(const float4*)&r1s[j * NR + lw];
        float r1v[4] = {ra.x, ra.y, ra.z, ra.w};
        #pragma unroll
        for (int ii = 0; ii < 4; ii++) {
            float r1 = r1v[ii];
            float r2 = fmaf(r1, r1, -1e-12f);
            #pragma unroll
            for (int c = 0; c < 4; c++) {
                float qh = fmaf(r1, w9h[c], fmaf(r2, w10h[c], u[ii][c] + vc[c]));
                float th = tanh_apx(qh);
                acc[ii][c] = fmaf(qh, th, acc[ii][c]);   // tanh part only
            }
        }
    }
    // subtract full diagonal silu (linear sums include j==i)
    #pragma unroll
    for (int ii = 0; ii < 4; ii++) {
        int li = lw + ii;
        int ig = R0 + li;
        float4 v4 = vs4[ig * 32 + l];
        float vc[4] = {v4.x, v4.y, v4.z, v4.w};
        float r1 = r1s[ig * NR + li];
        float r2 = fmaf(r1, r1, -1e-12f);
        #pragma unroll
        for (int c = 0; c < 4; c++) {
            float qh = fmaf(r1, w9h[c], fmaf(r2, w10h[c], u[ii][c] + vc[c]));
            float th = tanh_apx(qh);
            acc[ii][c] -= fmaf(qh, th, qh);   // qh + qh*th
        }
    }
    __syncthreads();   // all vs/r1s reads retired (sums done pre-loop)

    // H = linear + acc ; overlay into sb (stride 132, 32 rows)
    #pragma unroll
    for (int ii = 0; ii < 4; ii++) {
        int li = lw + ii;
        float s1 = S1[li], s2 = S2[li];
        float hv[4];
        #pragma unroll
        for (int c = 0; c < 4; c++) {
            float lin = fmaf(64.0f, u[ii][c], SV[kc + c]);
            lin = fmaf(w9h[c], s1, lin);
            lin = fmaf(w10h[c], s2, lin);
            hv[c] = lin + acc[ii][c];
        }
        *(float4*)&sb[li * 132 + kc] = make_float4(hv[0], hv[1], hv[2], hv[3]);
    }
    __syncthreads();

    // ---------------- Phase 2: psi via tf32 mma (rows R0..R0+31) ----------
    int mi = w & 1, nh = w >> 1;     // 2 m-tiles x 4 n-quarters
    int gi = l >> 2, qi = l & 3;
    int rA = mi * 16 + gi;           // local rows rA, rA+8
    int nbase = nh * 32;

    float C[4][4];
    int gr0 = R0 + rA, gr1 = R0 + rA + 8;
    float xr0[3] = {xb[gr0 * 3 + 0], xb[gr0 * 3 + 1], xb[gr0 * 3 + 2]};
    float xr1[3] = {xb[gr1 * 3 + 0], xb[gr1 * 3 + 1], xb[gr1 * 3 + 2]};

    #pragma unroll
    for (int tt = 0; tt < 4; tt++) {
        int nc = nbase + tt * 8 + qi * 2;
        #pragma unroll
        for (int h = 0; h < 2; h++) {
            float cc = g_c0[nc + h];
            float p0 = psi_w0[0 * MH + nc + h];
            float p1 = psi_w0[1 * MH + nc + h];
            float p2 = psi_w0[2 * MH + nc + h];
            C[tt][h]     = fmaf(xr0[2], p2, fmaf(xr0[1], p1, fmaf(xr0[0], p0, cc)));
            C[tt][2 + h] = fmaf(xr1[2], p2, fmaf(xr1[1], p1, fmaf(xr1[0], p0, cc)));
        }
    }

    // layer A: C += H @ Wfused
    {
        const float* sA0 = &sb[rA * 132];
        const float* sA1 = &sb[(rA + 8) * 132];
        const uint2* wp = &g_WfP[qi * MH + nbase + gi];
        #pragma unroll 1
        for (int kt = 0; kt < 16; kt++) {
            int k0 = kt * 8;
            unsigned a0 = tf32r(sA0[k0 + qi]);
            unsigned a1 = tf32r(sA1[k0 + qi]);
            unsigned a2 = tf32r(sA0[k0 + qi + 4]);
            unsigned a3 = tf32r(sA1[k0 + qi + 4]);
            #pragma unroll
            for (int tt = 0; tt < 4; tt++) {
                uint2 bb = wp[tt * 8];
                mma_tf32(C[tt], a0, a1, a2, a3, bb.x, bb.y);
            }
            wp += 4 * MH;
        }
    }
    __syncthreads();

    // silu -> h1 in shared
    #pragma unroll
    for (int tt = 0; tt < 4; tt++) {
        int nc = nbase + tt * 8 + qi * 2;
        *(float2*)&sb[rA * 132 + nc] =
            make_float2(silu_f(C[tt][0]), silu_f(C[tt][1]));
        *(float2*)&sb[(rA + 8) * 132 + nc] =
            make_float2(silu_f(C[tt][2]), silu_f(C[tt][3]));
    }
    __syncthreads();

    // layer B: C = psi_b1 + h1 @ psi_w1
    #pragma unroll
    for (int tt = 0; tt < 4; tt++) {
        int nc = nbase + tt * 8 + qi * 2;
        float bb0 = psi_b1[nc], bb1 = psi_b1[nc + 1];
        C[tt][0] = bb0; C[tt][1] = bb1; C[tt][2] = bb0; C[tt][3] = bb1;
    }
    {
        const float* sA0 = &sb[rA * 132];
        const float* sA1 = &sb[(rA + 8) * 132];
        const uint2* wp = &g_W1P[qi * MH + nbase + gi];
        #pragma unroll 1
        for (int kt = 0; kt < 16; kt++) {
            int k0 = kt * 8;
            unsigned a0 = tf32r(sA0[k0 + qi]);
            unsigned a1 = tf32r(sA1[k0 + qi]);
            unsigned a2 = tf32r(sA0[k0 + qi + 4]);
            unsigned a3 = tf32r(sA1[k0 + qi + 4]);
            #pragma unroll
            for (int tt = 0; tt < 4; tt++) {
                uint2 bb = wp[tt * 8];
                mma_tf32(C[tt], a0, a1, a2, a3, bb.x, bb.y);
            }
            wp += 4 * MH;
        }
    }

    // layer C: silu -> partial projection onto psi_w2 (exact fp32)
    float p0[3] = {0.f, 0.f, 0.f}, p1[3] = {0.f, 0.f, 0.f};
    #pragma unroll
    for (int tt = 0; tt < 4; tt++) {
        int nc = nbase + tt * 8 + qi * 2;
        float s00 = silu_f(C[tt][0]), s01 = silu_f(C[tt][1]);
        float s10 = silu_f(C[tt][2]), s11 = silu_f(C[tt][3]);
        #pragma unroll
        for (int oc = 0; oc < 3; oc++) {
            float wa = psi_w2[nc * 3 + oc];
            float wb = psi_w2[(nc + 1) * 3 + oc];
            p0[oc] = fmaf(s01, wb, fmaf(s00, wa, p0[oc]));
            p1[oc] = fmaf(s11, wb, fmaf(s10, wa, p1[oc]));
        }
    }
    #pragma unroll
    for (int oc = 0; oc < 3; oc++) {
        p0[oc] += __shfl_xor_sync(0xffffffffu, p0[oc], 1);
        p0[oc] += __shfl_xor_sync(0xffffffffu, p0[oc], 2);
        p1[oc] += __shfl_xor_sync(0xffffffffu, p1[oc], 1);
        p1[oc] += __shfl_xor_sync(0xffffffffu, p1[oc], 2);
    }
    if (qi == 0) {
        #pragma unroll
        for (int oc = 0; oc < 3; oc++) {
            part[nh * (NR * 3) + rA * 3 + oc] = p0[oc];
            part[nh * (NR * 3) + (rA + 8) * 3 + oc] = p1[oc];
        }
    }
    __syncthreads();

    if (t < NR * 3) {
        int r = t / 3, oc = t - r * 3;
        float p = part[r * 3 + oc] + part[96 + r * 3 + oc]
                + part[192 + r * 3 + oc] + part[288 + r * 3 + oc] + psi_b2[oc];
        out[(b * NN + R0 + r) * 3 + oc] = tanhf(p) * g_sp;
    }
}

// ---------------------------------------------------------------------------
// Inputs (metadata order): 0 x, 1 spin(unused), 2 phi_w0, 3 phi_b0, 4 phi_w1,
// 5 phi_b1, 6 psi_w0, 7 psi_b0, 8 psi_w1, 9 psi_b1, 10 psi_w2, 11 psi_b2,
// 12 bf_scale_raw. Output: float32 (512,64,3).
// ---------------------------------------------------------------------------
extern "C" void kernel_launch(void* const* d_in, const int* in_sizes, int n_in,
                              void* d_out, int out_size)
{
    const float* x      = (const float*)d_in[0];
    const float* phi_w0 = (const float*)d_in[2];
    const float* phi_b0 = (const float*)d_in[3];
    const float* phi_w1 = (const float*)d_in[4];
    const float* phi_b1 = (const float*)d_in[5];
    const float* psi_w0 = (const float*)d_in[6];
    const float* psi_b0 = (const float*)d_in[7];
    const float* psi_w1 = (const float*)d_in[8];
    const float* psi_b1 = (const float*)d_in[9];
    const float* psi_w2 = (const float*)d_in[10];
    const float* psi_b2 = (const float*)d_in[11];
    const float* bf     = (const float*)d_in[12];
    float* out = (float*)d_out;

    precompute_kernel<<<MH + 1, 256>>>(phi_w1, phi_b1, psi_w0, psi_b0, psi_w1, bf);
    fused_kernel<<<BB * 2, 256>>>(x, phi_w0, phi_b0, psi_w0,
                                  psi_b1, psi_w2, psi_b2, out);
}